// round 2
// baseline (speedup 1.0000x reference)
#include <cuda_runtime.h>

#define NB 32768
#define NK 8192
#define ND 256
#define BETA 0.25f

#define BM 128
#define BN 128
#define BD 32
#define SPAD 4
#define SLD (BM + SPAD)

// Scratch (no allocations allowed in kernel_launch).
__device__ float g_znorm[NB];
__device__ float g_enorm[NK];
__device__ int   g_idx[NB];
__device__ float g_partial[NB];

// ---------------------------------------------------------------------------
// Row squared-norms: one warp per row, vectorized float4 loads.
// which==0 -> z norms, which==1 -> emb norms.
// ---------------------------------------------------------------------------
__global__ void vq_rownorm_kernel(const float* __restrict__ x, int nrows, int which) {
    int gw   = (int)((blockIdx.x * (unsigned)blockDim.x + threadIdx.x) >> 5);
    int lane = threadIdx.x & 31;
    if (gw >= nrows) return;
    const float4* row = (const float4*)(x + (size_t)gw * ND);
    float4 v0 = row[lane];
    float4 v1 = row[lane + 32];
    float s = v0.x * v0.x + v0.y * v0.y + v0.z * v0.z + v0.w * v0.w
            + v1.x * v1.x + v1.y * v1.y + v1.z * v1.z + v1.w * v1.w;
#pragma unroll
    for (int off = 16; off > 0; off >>= 1)
        s += __shfl_down_sync(0xffffffffu, s, off);
    if (lane == 0) {
        if (which) g_enorm[gw] = s;
        else       g_znorm[gw] = s;
    }
}

// ---------------------------------------------------------------------------
// Fused distance-GEMM + running argmin.
// Grid: NB/BM blocks of 256 threads. Each block owns 128 z-rows, scans all
// K=8192 codes in tiles of 128, accumulating dot products over D in chunks
// of 32 through shared memory, 8x8 register tile per thread.
// dist = fmaf(-2, dot, ||z||^2 + ||e||^2)  -- single-rounded, matches the
// reference expression tree ((A + B) - (2z)@e^T) bit-for-bit given equal dots.
// Tie-break: ascending k with strict '<' keeps the lowest index (jnp.argmin).
// ---------------------------------------------------------------------------
__global__ __launch_bounds__(256, 2)
void vq_argmin_kernel(const float* __restrict__ z, const float* __restrict__ e) {
    __shared__ float smem[2 * BD * SLD + BN];   // zs | es | bsh  (~34 KB)
    float* zs  = smem;
    float* es  = smem + BD * SLD;
    float* bsh = smem + 2 * BD * SLD;

    int tid = threadIdx.x;
    int tx  = tid & 15;   // code sub-tile (8 codes)
    int ty  = tid >> 4;   // row sub-tile  (8 rows)
    int m0  = blockIdx.x * BM;

    float best[8];
    int   bidx[8];
#pragma unroll
    for (int i = 0; i < 8; i++) { best[i] = 3.4028235e38f; bidx[i] = 0; }

    float arow[8];
#pragma unroll
    for (int i = 0; i < 8; i++) arow[i] = g_znorm[m0 + ty * 8 + i];

    const int lc = tid & 31;   // d-column within chunk
    const int lr = tid >> 5;   // base row for tile loads

    for (int k0 = 0; k0 < NK; k0 += BN) {
        if (tid < BN) bsh[tid] = g_enorm[k0 + tid];

        float acc[8][8];
#pragma unroll
        for (int i = 0; i < 8; i++)
#pragma unroll
            for (int j = 0; j < 8; j++) acc[i][j] = 0.0f;

        for (int d0 = 0; d0 < ND; d0 += BD) {
            __syncthreads();   // protect smem tiles (and bsh on first pass)
#pragma unroll
            for (int rr = 0; rr < BM; rr += 8) {
                zs[lc * SLD + lr + rr] = z[(size_t)(m0 + lr + rr) * ND + d0 + lc];
                es[lc * SLD + lr + rr] = e[(size_t)(k0 + lr + rr) * ND + d0 + lc];
            }
            __syncthreads();
#pragma unroll 8
            for (int dd = 0; dd < BD; dd++) {
                float4 za0 = *(const float4*)&zs[dd * SLD + ty * 8];
                float4 za1 = *(const float4*)&zs[dd * SLD + ty * 8 + 4];
                float4 eb0 = *(const float4*)&es[dd * SLD + tx * 8];
                float4 eb1 = *(const float4*)&es[dd * SLD + tx * 8 + 4];
                float za[8] = {za0.x, za0.y, za0.z, za0.w, za1.x, za1.y, za1.z, za1.w};
                float eb[8] = {eb0.x, eb0.y, eb0.z, eb0.w, eb1.x, eb1.y, eb1.z, eb1.w};
#pragma unroll
                for (int i = 0; i < 8; i++)
#pragma unroll
                    for (int j = 0; j < 8; j++)
                        acc[i][j] = fmaf(za[i], eb[j], acc[i][j]);
            }
        }

        // Epilogue: distances + running argmin for this code tile.
#pragma unroll
        for (int i = 0; i < 8; i++) {
#pragma unroll
            for (int j = 0; j < 8; j++) {
                float dv = fmaf(-2.0f, acc[i][j], arow[i] + bsh[tx * 8 + j]);
                int   kk = k0 + tx * 8 + j;
                if (dv < best[i]) { best[i] = dv; bidx[i] = kk; }
            }
        }
        __syncthreads();   // bsh is rewritten at top of next tile
    }

    // Cross-thread reduction: 16 threads (tx) share each of the 128 rows.
    float* rval = smem;                       // BM*16 floats
    int*   ridx = (int*)(smem + BM * 16);     // BM*16 ints
#pragma unroll
    for (int i = 0; i < 8; i++) {
        rval[(ty * 8 + i) * 16 + tx] = best[i];
        ridx[(ty * 8 + i) * 16 + tx] = bidx[i];
    }
    __syncthreads();
    if (tid < BM) {
        float bv = rval[tid * 16];
        int   bi = ridx[tid * 16];
#pragma unroll
        for (int t = 1; t < 16; t++) {
            float v  = rval[tid * 16 + t];
            int   ix = ridx[tid * 16 + t];
            if (v < bv || (v == bv && ix < bi)) { bv = v; bi = ix; }
        }
        g_idx[m0 + tid] = bi;
    }
}

// ---------------------------------------------------------------------------
// Gather + straight-through output + per-row loss partial + index output.
// One block per row, 256 threads = 256 dims. No atomics (deterministic).
// ---------------------------------------------------------------------------
__global__ void vq_gather_kernel(const float* __restrict__ z,
                                 const float* __restrict__ e,
                                 float* __restrict__ out) {
    int row = blockIdx.x;
    int t   = threadIdx.x;
    int idx = g_idx[row];

    float zv = z[(size_t)row * ND + t];
    float ev = e[(size_t)idx * ND + t];
    float d  = ev - zv;                         // fl(z_q - z)
    out[(size_t)row * ND + t] = zv + d;         // z + stopgrad(z_q - z)
    float sq = d * d;

#pragma unroll
    for (int off = 16; off > 0; off >>= 1)
        sq += __shfl_down_sync(0xffffffffu, sq, off);

    __shared__ float red[8];
    if ((t & 31) == 0) red[t >> 5] = sq;
    __syncthreads();
    if (t < 8) {
        float v = red[t];
#pragma unroll
        for (int off = 4; off > 0; off >>= 1)
            v += __shfl_down_sync(0xffu, v, off);
        if (t == 0) g_partial[row] = v;
    }
    if (t == 0) out[(size_t)NB * ND + 2 + row] = (float)idx;
}

// ---------------------------------------------------------------------------
// Final scalar reduction: sums per-row loss partials, writes both losses.
// ---------------------------------------------------------------------------
__global__ void vq_finalize_kernel(float* __restrict__ out) {
    int t = threadIdx.x;
    float s = 0.0f;
    for (int i = t; i < NB; i += 256) s += g_partial[i];
#pragma unroll
    for (int off = 16; off > 0; off >>= 1)
        s += __shfl_down_sync(0xffffffffu, s, off);
    __shared__ float red[8];
    if ((t & 31) == 0) red[t >> 5] = s;
    __syncthreads();
    if (t == 0) {
        float tot = 0.0f;
#pragma unroll
        for (int w = 0; w < 8; w++) tot += red[w];
        float l = BETA * (tot / (float)((size_t)NB * ND));
        out[(size_t)NB * ND]     = l;   // vq_loss
        out[(size_t)NB * ND + 1] = l;   // commit (numerically identical)
    }
}

extern "C" void kernel_launch(void* const* d_in, const int* in_sizes, int n_in,
                              void* d_out, int out_size) {
    const float* z = (const float*)d_in[0];
    const float* e = (const float*)d_in[1];
    float* out = (float*)d_out;

    vq_rownorm_kernel<<<(NB * 32 + 255) / 256, 256>>>(z, NB, 0);
    vq_rownorm_kernel<<<(NK * 32 + 255) / 256, 256>>>(e, NK, 1);
    vq_argmin_kernel<<<NB / BM, 256>>>(z, e);
    vq_gather_kernel<<<NB, 256>>>(z, e, out);
    vq_finalize_kernel<<<1, 256>>>(out);
}